// round 16
// baseline (speedup 1.0000x reference)
#include <cuda_runtime.h>

#define L_SEQ 512
#define T_TAGS 64
#define CHAINS 8          // chains per CTA (2 per warp)
#define THREADS 128
#define PFD 4             // emission prefetch depth (pre-exponentiated)

#define FMA2(d, a, b) asm("fma.rn.f32x2 %0, %1, %2, %0;" : "+l"(d) : "l"(a), "l"(b))
#define ADD2(d, a)    asm("add.rn.f32x2 %0, %0, %1;"      : "+l"(d) : "l"(a))

__device__ __forceinline__ unsigned long long pack2(float x, float y) {
    unsigned long long r;
    asm("mov.b64 %0, {%1, %2};" : "=l"(r) : "f"(x), "f"(y));
    return r;
}

__global__ __launch_bounds__(THREADS, 1)
void crf_kernel(const float* __restrict__ logits,
                const unsigned int* __restrict__ tagw,
                const int* __restrict__ mask,
                const float* __restrict__ trans,
                float* __restrict__ out)
{
    // u buffers: 64 floats per chain, double-buffered; 68 pad keeps 16B alignment
    __shared__ __align__(16) float ubuf[2][CHAINS][68];

    const int tid  = threadIdx.x;
    const int w    = tid >> 5;          // warp: owns chains 2w, 2w+1
    const int lane = tid & 31;
    const int j0   = lane << 1;         // this lane owns tags j0, j0+1
    const int ca   = 2 * w;
    const int cb   = 2 * w + 1;
    const int bA   = blockIdx.x * CHAINS + ca;
    const int bB   = bA + 1;

    // ---- tag dtype detection (int64 LE => odd 32-bit words all zero) ----
    unsigned oddacc = 0;
    #pragma unroll
    for (int k = 0; k < 4; ++k) oddacc |= tagw[2 * (lane + 32 * k) + 1];
    const int is64 = __all_sync(0xffffffffu, oddacc == 0) ? 1 : 0;

    // ---- register cache of exp(trans): columns j0, j0+1 (shared by both chains) ----
    unsigned long long ec0[32], ec1[32];
    #pragma unroll
    for (int m = 0; m < 32; ++m) {
        float2 ta = *(const float2*)&trans[(2 * m) * 64 + j0];
        float2 tb = *(const float2*)&trans[(2 * m + 1) * 64 + j0];
        ec0[m] = pack2(__expf(ta.x), __expf(tb.x));
        ec1[m] = pack2(__expf(ta.y), __expf(tb.y));
    }

    const float*  lgA  = logits + (size_t)bA * (L_SEQ * T_TAGS);
    const float*  lgB  = logits + (size_t)bB * (L_SEQ * T_TAGS);
    const float2* lgA2 = (const float2*)lgA;
    const float2* lgB2 = (const float2*)lgB;
    const int mbA = bA * L_SEQ;
    const int mbB = bB * L_SEQ;

    // ---- gold score prologue (parallel gather), both chains ----
    float gpA = 0.f, gpB = 0.f;
    int mok = 1;
    #pragma unroll
    for (int k = 0; k < 16; ++k) {
        const int l = lane + 32 * k;
        {
            const int mi = mask[mbA + l];
            mok &= (mi == 1);
            const int tg = (int)tagw[is64 ? ((mbA + l) << 1) : (mbA + l)];
            float fm = (float)mi;
            gpA += fm * lgA[l * T_TAGS + tg];
            if (l > 0) {
                const int tp = (int)tagw[is64 ? ((mbA + l - 1) << 1) : (mbA + l - 1)];
                gpA += fm * __ldg(&trans[tp * 64 + tg]);
            }
        }
        {
            const int mi = mask[mbB + l];
            mok &= (mi == 1);
            const int tg = (int)tagw[is64 ? ((mbB + l) << 1) : (mbB + l)];
            float fm = (float)mi;
            gpB += fm * lgB[l * T_TAGS + tg];
            if (l > 0) {
                const int tp = (int)tagw[is64 ? ((mbB + l - 1) << 1) : (mbB + l - 1)];
                gpB += fm * __ldg(&trans[tp * 64 + tg]);
            }
        }
    }
    mok = __all_sync(0xffffffffu, mok) ? 1 : 0;

    // ---- init: u = exp(alpha0 - alpha0[0]); lr carries the log offset ----
    const float a00A = __ldg(lgA);
    const float a00B = __ldg(lgB);
    float2 avA = lgA2[lane];
    float2 avB = lgB2[lane];
    float muA0 = __expf(avA.x - a00A), muA1 = __expf(avA.y - a00A);
    float muB0 = __expf(avB.x - a00B), muB1 = __expf(avB.y - a00B);
    *(float2*)&ubuf[1][ca][j0] = make_float2(muA0, muA1);
    *(float2*)&ubuf[1][cb][j0] = make_float2(muB0, muB1);
    float lrA = a00A, lrB = a00B;

    // ---- emission rings, PRE-EXPONENTIATED ----
    float2 eemA[PFD], eemB[PFD];
    #pragma unroll
    for (int k = 0; k < PFD; ++k) {
        float2 ea = __ldg(&lgA2[(1 + k) * 32 + lane]);
        float2 eb = __ldg(&lgB2[(1 + k) * 32 + lane]);
        eemA[k] = make_float2(__expf(ea.x), __expf(ea.y));
        eemB[k] = make_float2(__expf(eb.x), __expf(eb.y));
    }
    __syncwarp();

    if (mok) {
        // ======== hot loop: two interleaved linear-space chains ========
        for (int l = 1; l < L_SEQ; ++l) {
            const int slot = (l - 1) & (PFD - 1);
            float2 fA = eemA[slot], fB = eemB[slot];
            const int lp = (l + PFD < L_SEQ) ? (l + PFD) : (L_SEQ - 1);
            float2 rawA = __ldg(&lgA2[lp * 32 + lane]);
            float2 rawB = __ldg(&lgB2[lp * 32 + lane]);

            const ulonglong2* pqA = (const ulonglong2*)&ubuf[l & 1][ca][0];
            const ulonglong2* pqB = (const ulonglong2*)&ubuf[l & 1][cb][0];

            unsigned long long A0 = 0, B0 = 0, A1 = 0, B1 = 0;   // chain A accums
            unsigned long long X0 = 0, Y0 = 0, X1 = 0, Y1 = 0;   // chain B accums
            float u0A, u0B, dmy;
            #pragma unroll
            for (int k = 0; k < 16; ++k) {
                ulonglong2 pa = pqA[k];
                ulonglong2 pb = pqB[k];
                if (k == 0) {
                    asm("mov.b64 {%0, %1}, %2;" : "=f"(u0A), "=f"(dmy) : "l"(pa.x));
                    asm("mov.b64 {%0, %1}, %2;" : "=f"(u0B), "=f"(dmy) : "l"(pb.x));
                }
                FMA2(A0, pa.x, ec0[2 * k]);     FMA2(X0, pb.x, ec0[2 * k]);
                FMA2(A1, pa.x, ec1[2 * k]);     FMA2(X1, pb.x, ec1[2 * k]);
                FMA2(B0, pa.y, ec0[2 * k + 1]); FMA2(Y0, pb.y, ec0[2 * k + 1]);
                FMA2(B1, pa.y, ec1[2 * k + 1]); FMA2(Y1, pb.y, ec1[2 * k + 1]);
            }

            // off-path: ring refill, normalizers, log-carries
            eemA[slot] = make_float2(__expf(rawA.x), __expf(rawA.y));
            eemB[slot] = make_float2(__expf(rawB.x), __expf(rawB.y));
            float rA, rB;
            asm("rcp.approx.ftz.f32 %0, %1;" : "=f"(rA) : "f"(u0A));
            asm("rcp.approx.ftz.f32 %0, %1;" : "=f"(rB) : "f"(u0B));
            lrA += __logf(u0A);
            lrB += __logf(u0B);

            ADD2(A0, B0); ADD2(A1, B1);
            ADD2(X0, Y0); ADD2(X1, Y1);
            float a0lo, a0hi, a1lo, a1hi, x0lo, x0hi, x1lo, x1hi;
            asm("mov.b64 {%0, %1}, %2;" : "=f"(a0lo), "=f"(a0hi) : "l"(A0));
            asm("mov.b64 {%0, %1}, %2;" : "=f"(a1lo), "=f"(a1hi) : "l"(A1));
            asm("mov.b64 {%0, %1}, %2;" : "=f"(x0lo), "=f"(x0hi) : "l"(X0));
            asm("mov.b64 {%0, %1}, %2;" : "=f"(x1lo), "=f"(x1hi) : "l"(X1));

            muA0 = (a0lo + a0hi) * (fA.x * rA);
            muA1 = (a1lo + a1hi) * (fA.y * rA);
            muB0 = (x0lo + x0hi) * (fB.x * rB);
            muB1 = (x1lo + x1hi) * (fB.y * rB);
            *(float2*)&ubuf[(l + 1) & 1][ca][j0] = make_float2(muA0, muA1);
            *(float2*)&ubuf[(l + 1) & 1][cb][j0] = make_float2(muB0, muB1);
            __syncwarp();
        }
    } else {
        // ======== fallback: masked steps (uniform-scaling exact) ========
        for (int l = 1; l < L_SEQ; ++l) {
            const int slot = (l - 1) & (PFD - 1);
            float2 fA = eemA[slot], fB = eemB[slot];
            const int lp = (l + PFD < L_SEQ) ? (l + PFD) : (L_SEQ - 1);
            float2 rawA = __ldg(&lgA2[lp * 32 + lane]);
            float2 rawB = __ldg(&lgB2[lp * 32 + lane]);
            const int cmA = mask[mbA + l];
            const int cmB = mask[mbB + l];

            const ulonglong2* pqA = (const ulonglong2*)&ubuf[l & 1][ca][0];
            const ulonglong2* pqB = (const ulonglong2*)&ubuf[l & 1][cb][0];

            unsigned long long A0 = 0, B0 = 0, A1 = 0, B1 = 0;
            unsigned long long X0 = 0, Y0 = 0, X1 = 0, Y1 = 0;
            float u0A, u0B, dmy;
            #pragma unroll
            for (int k = 0; k < 16; ++k) {
                ulonglong2 pa = pqA[k];
                ulonglong2 pb = pqB[k];
                if (k == 0) {
                    asm("mov.b64 {%0, %1}, %2;" : "=f"(u0A), "=f"(dmy) : "l"(pa.x));
                    asm("mov.b64 {%0, %1}, %2;" : "=f"(u0B), "=f"(dmy) : "l"(pb.x));
                }
                FMA2(A0, pa.x, ec0[2 * k]);     FMA2(X0, pb.x, ec0[2 * k]);
                FMA2(A1, pa.x, ec1[2 * k]);     FMA2(X1, pb.x, ec1[2 * k]);
                FMA2(B0, pa.y, ec0[2 * k + 1]); FMA2(Y0, pb.y, ec0[2 * k + 1]);
                FMA2(B1, pa.y, ec1[2 * k + 1]); FMA2(Y1, pb.y, ec1[2 * k + 1]);
            }

            eemA[slot] = make_float2(__expf(rawA.x), __expf(rawA.y));
            eemB[slot] = make_float2(__expf(rawB.x), __expf(rawB.y));
            float rA, rB;
            asm("rcp.approx.ftz.f32 %0, %1;" : "=f"(rA) : "f"(u0A));
            asm("rcp.approx.ftz.f32 %0, %1;" : "=f"(rB) : "f"(u0B));
            lrA += __logf(u0A);
            lrB += __logf(u0B);

            ADD2(A0, B0); ADD2(A1, B1);
            ADD2(X0, Y0); ADD2(X1, Y1);
            float a0lo, a0hi, a1lo, a1hi, x0lo, x0hi, x1lo, x1hi;
            asm("mov.b64 {%0, %1}, %2;" : "=f"(a0lo), "=f"(a0hi) : "l"(A0));
            asm("mov.b64 {%0, %1}, %2;" : "=f"(a1lo), "=f"(a1hi) : "l"(A1));
            asm("mov.b64 {%0, %1}, %2;" : "=f"(x0lo), "=f"(x0hi) : "l"(X0));
            asm("mov.b64 {%0, %1}, %2;" : "=f"(x1lo), "=f"(x1hi) : "l"(X1));

            float nA0 = (a0lo + a0hi) * (fA.x * rA);
            float nA1 = (a1lo + a1hi) * (fA.y * rA);
            float nB0 = (x0lo + x0hi) * (fB.x * rB);
            float nB1 = (x1lo + x1hi) * (fB.y * rB);
            muA0 = (cmA > 0) ? nA0 : muA0 * rA;
            muA1 = (cmA > 0) ? nA1 : muA1 * rA;
            muB0 = (cmB > 0) ? nB0 : muB0 * rB;
            muB1 = (cmB > 0) ? nB1 : muB1 * rB;
            *(float2*)&ubuf[(l + 1) & 1][ca][j0] = make_float2(muA0, muA1);
            *(float2*)&ubuf[(l + 1) & 1][cb][j0] = make_float2(muB0, muB1);
            __syncwarp();
        }
    }

    // ---- epilogue: logZ = lr + log(sum u) per chain; subtract gold ----
    float suA = muA0 + muA1;
    float suB = muB0 + muB1;
    #pragma unroll
    for (int d = 1; d < 32; d <<= 1) {
        suA += __shfl_xor_sync(0xffffffffu, suA, d);
        suB += __shfl_xor_sync(0xffffffffu, suB, d);
        gpA += __shfl_xor_sync(0xffffffffu, gpA, d);
        gpB += __shfl_xor_sync(0xffffffffu, gpB, d);
    }

    if (lane == 0) {
        out[bA] = (lrA + __logf(suA)) - gpA;
        out[bB] = (lrB + __logf(suB)) - gpB;
    }
}

extern "C" void kernel_launch(void* const* d_in, const int* in_sizes, int n_in,
                              void* d_out, int out_size)
{
    const float*        logits = (const float*)d_in[0];
    const unsigned int* tagw   = (const unsigned int*)d_in[1];
    const int*          mask   = (const int*)d_in[2];
    const float*        trans  = (const float*)d_in[3];
    float*              out    = (float*)d_out;

    crf_kernel<<<128, THREADS>>>(logits, tagw, mask, trans, out);
}

// round 17
// speedup vs baseline: 2.0623x; 2.0623x over previous
#include <cuda_runtime.h>

#define L_SEQ 512
#define T_TAGS 64
#define CHAINS 8          // one warp per chain
#define THREADS 256
#define PFD 4             // emission prefetch depth (pre-exponentiated)

#define FMA2(d, a, b) asm("fma.rn.f32x2 %0, %1, %2, %0;" : "+l"(d) : "l"(a), "l"(b))
#define ADD2(d, a)    asm("add.rn.f32x2 %0, %0, %1;"      : "+l"(d) : "l"(a))

__device__ __forceinline__ unsigned long long pack2(float x, float y) {
    unsigned long long r;
    asm("mov.b64 %0, {%1, %2};" : "=l"(r) : "f"(x), "f"(y));
    return r;
}

// Software-pipelined 64x2 matvec: s[j0], s[j0+1] from broadcast u in smem,
// expT columns in registers. Also extracts u[0].
#define MATVEC(pq, ec0, ec1, s0out, s1out, u0out) do {                         \
    ulonglong2 q0 = (pq)[0], q1 = (pq)[1], q2 = (pq)[2], q3 = (pq)[3];         \
    float _dm;                                                                 \
    asm("mov.b64 {%0, %1}, %2;" : "=f"(u0out), "=f"(_dm) : "l"(q0.x));         \
    unsigned long long A0 = 0, B0 = 0, C0 = 0, D0 = 0;                         \
    unsigned long long A1 = 0, B1 = 0, C1 = 0, D1 = 0;                         \
    _Pragma("unroll")                                                          \
    for (int t = 0; t < 4; ++t) {                                              \
        ulonglong2 n0, n1, n2, n3;                                             \
        if (t < 3) {                                                           \
            n0 = (pq)[4 * t + 4]; n1 = (pq)[4 * t + 5];                        \
            n2 = (pq)[4 * t + 6]; n3 = (pq)[4 * t + 7];                        \
        }                                                                      \
        FMA2(A0, q0.x, ec0[8 * t + 0]); FMA2(A1, q0.x, ec1[8 * t + 0]);        \
        FMA2(B0, q0.y, ec0[8 * t + 1]); FMA2(B1, q0.y, ec1[8 * t + 1]);        \
        FMA2(C0, q1.x, ec0[8 * t + 2]); FMA2(C1, q1.x, ec1[8 * t + 2]);        \
        FMA2(D0, q1.y, ec0[8 * t + 3]); FMA2(D1, q1.y, ec1[8 * t + 3]);        \
        FMA2(A0, q2.x, ec0[8 * t + 4]); FMA2(A1, q2.x, ec1[8 * t + 4]);        \
        FMA2(B0, q2.y, ec0[8 * t + 5]); FMA2(B1, q2.y, ec1[8 * t + 5]);        \
        FMA2(C0, q3.x, ec0[8 * t + 6]); FMA2(C1, q3.x, ec1[8 * t + 6]);        \
        FMA2(D0, q3.y, ec0[8 * t + 7]); FMA2(D1, q3.y, ec1[8 * t + 7]);        \
        if (t < 3) { q0 = n0; q1 = n1; q2 = n2; q3 = n3; }                     \
    }                                                                          \
    ADD2(A0, B0); ADD2(C0, D0); ADD2(A0, C0);                                  \
    ADD2(A1, B1); ADD2(C1, D1); ADD2(A1, C1);                                  \
    float _s0lo, _s0hi, _s1lo, _s1hi;                                          \
    asm("mov.b64 {%0, %1}, %2;" : "=f"(_s0lo), "=f"(_s0hi) : "l"(A0));         \
    asm("mov.b64 {%0, %1}, %2;" : "=f"(_s1lo), "=f"(_s1hi) : "l"(A1));         \
    s0out = _s0lo + _s0hi;                                                     \
    s1out = _s1lo + _s1hi;                                                     \
} while (0)

__global__ __launch_bounds__(THREADS, 1)
void crf_kernel(const float* __restrict__ logits,
                const unsigned int* __restrict__ tagw,
                const int* __restrict__ mask,
                const float* __restrict__ trans,
                float* __restrict__ out)
{
    __shared__ __align__(16) float ubuf[2][CHAINS][68];

    const int tid  = threadIdx.x;
    const int w    = tid >> 5;
    const int lane = tid & 31;
    const int j0   = lane << 1;
    const int b    = blockIdx.x * CHAINS + w;

    // ---- tag dtype detection (int64 LE => odd 32-bit words all zero) ----
    unsigned oddacc = 0;
    #pragma unroll
    for (int k = 0; k < 4; ++k) oddacc |= tagw[2 * (lane + 32 * k) + 1];
    const int is64 = __all_sync(0xffffffffu, oddacc == 0) ? 1 : 0;

    // ---- register cache of exp(trans): columns j0, j0+1 ----
    unsigned long long ec0[32], ec1[32];
    #pragma unroll
    for (int m = 0; m < 32; ++m) {
        float2 ta = *(const float2*)&trans[(2 * m) * 64 + j0];
        float2 tb = *(const float2*)&trans[(2 * m + 1) * 64 + j0];
        ec0[m] = pack2(__expf(ta.x), __expf(tb.x));
        ec1[m] = pack2(__expf(ta.y), __expf(tb.y));
    }

    const float*  lg  = logits + (size_t)b * (L_SEQ * T_TAGS);
    const float2* lg2 = (const float2*)lg;
    const int mbase = b * L_SEQ;

    // ---- gold score prologue (parallel gather) ----
    float gp = 0.f;
    int mok = 1;
    #pragma unroll
    for (int k = 0; k < 16; ++k) {
        const int l = lane + 32 * k;
        const int mi = mask[mbase + l];
        mok &= (mi == 1);
        const int tg = (int)tagw[is64 ? ((mbase + l) << 1) : (mbase + l)];
        float fm = (float)mi;
        gp += fm * lg[l * T_TAGS + tg];
        if (l > 0) {
            const int tp = (int)tagw[is64 ? ((mbase + l - 1) << 1) : (mbase + l - 1)];
            gp += fm * __ldg(&trans[tp * 64 + tg]);
        }
    }
    mok = __all_sync(0xffffffffu, mok) ? 1 : 0;

    // ---- init ----
    const float a00 = __ldg(lg);
    float2 alv = lg2[lane];
    float mu0 = __expf(alv.x - a00);
    float mu1 = __expf(alv.y - a00);
    *(float2*)&ubuf[1][w][j0] = make_float2(mu0, mu1);   // step 1 reads buf 1
    float lr = a00;

    // ---- emission ring, pre-exponentiated ----
    float2 eem[PFD];
    #pragma unroll
    for (int k = 0; k < PFD; ++k) {
        float2 e = __ldg(&lg2[(1 + k) * 32 + lane]);
        eem[k] = make_float2(__expf(e.x), __expf(e.y));
    }
    __syncwarp();

    if (mok) {
        // ======== hot loop: pairs of steps; renorm only on 2nd ========
        for (int l = 1; l + 1 < L_SEQ; l += 2) {
            // ---- step l: NO renorm ----
            {
                const int slot = (l - 1) & (PFD - 1);
                float2 f = eem[slot];
                float2 raw = __ldg(&lg2[(l + PFD) * 32 + lane]);  // l+PFD<=513, clamp not needed while l+1<512 => l<=509, l+PFD=513>511? guard:
                // (l max 509 -> l+PFD = 513 out of range; clamp)
                // NOTE: clamped below via min index
                (void)raw;
                const int lp = (l + PFD < L_SEQ) ? (l + PFD) : (L_SEQ - 1);
                raw = __ldg(&lg2[lp * 32 + lane]);

                const ulonglong2* pq = (const ulonglong2*)&ubuf[l & 1][w][0];
                float s0, s1, u0f;
                MATVEC(pq, ec0, ec1, s0, s1, u0f);
                eem[slot] = make_float2(__expf(raw.x), __expf(raw.y));

                mu0 = s0 * f.x;
                mu1 = s1 * f.y;
                *(float2*)&ubuf[(l + 1) & 1][w][j0] = make_float2(mu0, mu1);
                __syncwarp();
            }
            // ---- step l+1: renorm by u[0] ----
            {
                const int l2 = l + 1;
                const int slot = (l2 - 1) & (PFD - 1);
                float2 f = eem[slot];
                const int lp = (l2 + PFD < L_SEQ) ? (l2 + PFD) : (L_SEQ - 1);
                float2 raw = __ldg(&lg2[lp * 32 + lane]);

                const ulonglong2* pq = (const ulonglong2*)&ubuf[l2 & 1][w][0];
                float s0, s1, u0f;
                MATVEC(pq, ec0, ec1, s0, s1, u0f);
                eem[slot] = make_float2(__expf(raw.x), __expf(raw.y));

                float r;
                asm("rcp.approx.ftz.f32 %0, %1;" : "=f"(r) : "f"(u0f));
                lr += __logf(u0f);

                mu0 = s0 * (f.x * r);
                mu1 = s1 * (f.y * r);
                *(float2*)&ubuf[(l2 + 1) & 1][w][j0] = make_float2(mu0, mu1);
                __syncwarp();
            }
        }
        // ---- final step (l = 511), with renorm ----
        {
            const int l2 = L_SEQ - 1;
            const int slot = (l2 - 1) & (PFD - 1);
            float2 f = eem[slot];

            const ulonglong2* pq = (const ulonglong2*)&ubuf[l2 & 1][w][0];
            float s0, s1, u0f;
            MATVEC(pq, ec0, ec1, s0, s1, u0f);

            float r;
            asm("rcp.approx.ftz.f32 %0, %1;" : "=f"(r) : "f"(u0f));
            lr += __logf(u0f);

            mu0 = s0 * (f.x * r);
            mu1 = s1 * (f.y * r);
        }
    } else {
        // ======== fallback: per-step renorm + mask select ========
        for (int l = 1; l < L_SEQ; ++l) {
            const int slot = (l - 1) & (PFD - 1);
            float2 f = eem[slot];
            const int lp = (l + PFD < L_SEQ) ? (l + PFD) : (L_SEQ - 1);
            float2 raw = __ldg(&lg2[lp * 32 + lane]);
            const int cm = mask[mbase + l];

            const ulonglong2* pq = (const ulonglong2*)&ubuf[l & 1][w][0];
            float s0, s1, u0f;
            MATVEC(pq, ec0, ec1, s0, s1, u0f);
            eem[slot] = make_float2(__expf(raw.x), __expf(raw.y));

            float r;
            asm("rcp.approx.ftz.f32 %0, %1;" : "=f"(r) : "f"(u0f));
            lr += __logf(u0f);

            float n0 = s0 * (f.x * r);
            float n1 = s1 * (f.y * r);
            mu0 = (cm > 0) ? n0 : mu0 * r;
            mu1 = (cm > 0) ? n1 : mu1 * r;
            *(float2*)&ubuf[(l + 1) & 1][w][j0] = make_float2(mu0, mu1);
            __syncwarp();
        }
    }

    // ---- epilogue: logZ = lr + log(sum u); subtract gold ----
    float su = mu0 + mu1;
    #pragma unroll
    for (int d = 1; d < 32; d <<= 1)
        su += __shfl_xor_sync(0xffffffffu, su, d);
    #pragma unroll
    for (int d = 1; d < 32; d <<= 1)
        gp += __shfl_xor_sync(0xffffffffu, gp, d);

    if (lane == 0)
        out[b] = (lr + __logf(su)) - gp;
}

extern "C" void kernel_launch(void* const* d_in, const int* in_sizes, int n_in,
                              void* d_out, int out_size)
{
    const float*        logits = (const float*)d_in[0];
    const unsigned int* tagw   = (const unsigned int*)d_in[1];
    const int*          mask   = (const int*)d_in[2];
    const float*        trans  = (const float*)d_in[3];
    float*              out    = (float*)d_out;

    crf_kernel<<<128, THREADS>>>(logits, tagw, mask, trans, out);
}